// round 12
// baseline (speedup 1.0000x reference)
#include <cuda_runtime.h>
#include <cuda_fp16.h>
#include <cstdint>

// Problem constants (fixed shapes for this instance)
#define N_NODES 50000
#define N_EDGES 600000
#define CH      128          // IN_CH == OUT_CH == 128, HEADS == 1
#define CAP     96           // per-node bucket capacity
#define OVF_MAX 16384        // overflow edge list capacity (correctness fallback)

#define LDA 136              // padded fp16 row stride (272 B) for ldmatrix tiles

// ---------------------------------------------------------------------------
// Scratch (no cudaMalloc allowed)
// ---------------------------------------------------------------------------
__device__ __half d_xh[(size_t)N_NODES * CH];      // x in fp16
__device__ __half d_sh[(size_t)N_NODES * CH];      // aggregated features, fp16
__device__ int    d_deg[N_NODES];                  // in-degree (excl. self loop)
__device__ int    d_bucket[(size_t)N_NODES * CAP]; // per-dst source lists
__device__ int    d_is64;                          // edge_index dtype flag
__device__ int    d_ovf_cnt;
__device__ int    d_ovf[OVF_MAX * 2];
__device__ __half d_Wh[CH * LDA];                  // W^T [n][k], fp16, padded

// ---------------------------------------------------------------------------
// MMA helpers (baseline PTX, legal on plain sm_103)
// ---------------------------------------------------------------------------
__device__ __forceinline__ uint32_t smem_to_u32(const void* p) {
    uint32_t a;
    asm("{ .reg .u64 t; cvta.to.shared.u64 t, %1; cvt.u32.u64 %0, t; }"
        : "=r"(a) : "l"(p));
    return a;
}
__device__ __forceinline__ void ldsm_x4(uint32_t* r, uint32_t addr) {
    asm volatile("ldmatrix.sync.aligned.m8n8.x4.shared.b16 {%0,%1,%2,%3}, [%4];"
                 : "=r"(r[0]), "=r"(r[1]), "=r"(r[2]), "=r"(r[3]) : "r"(addr));
}
__device__ __forceinline__ void mma_fp16(float* c, const uint32_t* a,
                                         uint32_t b0, uint32_t b1) {
    asm volatile("mma.sync.aligned.m16n8k16.row.col.f32.f16.f16.f32 "
                 "{%0,%1,%2,%3}, {%4,%5,%6,%7}, {%8,%9}, {%0,%1,%2,%3};"
                 : "+f"(c[0]), "+f"(c[1]), "+f"(c[2]), "+f"(c[3])
                 : "r"(a[0]), "r"(a[1]), "r"(a[2]), "r"(a[3]), "r"(b0), "r"(b1));
}

// ---------------------------------------------------------------------------
// Zero: deg = 0, ovf = 0, dtype sniff. Small & fast; precedes histo.
// ---------------------------------------------------------------------------
__global__ void zero_kernel(const void* __restrict__ ei, int n_nodes) {
    int i = blockIdx.x * blockDim.x + threadIdx.x;
    if (i < n_nodes) d_deg[i] = 0;
    if (i == 0) {
        d_ovf_cnt = 0;
        const unsigned long long* p = (const unsigned long long*)ei;
        int is64 = 1;
        #pragma unroll
        for (int j = 0; j < 16; j++)
            if (p[j] >> 32) is64 = 0;
        d_is64 = is64;
    }
}

// ---------------------------------------------------------------------------
// Prep: x -> fp16, W -> fp16 [n][k] padded. Independent of deg/histo
// (runs on a forked stream, overlapped with histo).
// ---------------------------------------------------------------------------
__global__ void prep_kernel(const float* __restrict__ x,
                            const float* __restrict__ W, int n_nodes) {
    int i = blockIdx.x * blockDim.x + threadIdx.x;
    int n4 = n_nodes * (CH / 4);
    if (i < n4) {
        float4 v = *(const float4*)(x + (size_t)i * 4);
        __half2 h01 = __floats2half2_rn(v.x, v.y);
        __half2 h23 = __floats2half2_rn(v.z, v.w);
        uint2 pack;
        pack.x = *(uint32_t*)&h01;
        pack.y = *(uint32_t*)&h23;
        *(uint2*)(d_xh + (size_t)i * 4) = pack;
    }
    if (i < CH * LDA) {
        int n = i / LDA;
        int k = i % LDA;
        float w = (k < CH) ? W[(size_t)k * CH + n] : 0.0f;
        d_Wh[i] = __float2half_rn(w);
    }
}

// ---------------------------------------------------------------------------
// Histogram + bucket fill: 2 edges per thread, vectorized index loads.
// ---------------------------------------------------------------------------
__device__ __forceinline__ void histo_one(int src, int dst) {
    int pos = atomicAdd(&d_deg[dst], 1);
    if (pos < CAP) {
        d_bucket[dst * CAP + pos] = src;
    } else {
        int j = atomicAdd(&d_ovf_cnt, 1);
        if (j < OVF_MAX) { d_ovf[2 * j] = src; d_ovf[2 * j + 1] = dst; }
    }
}

__global__ void histo_fill_kernel(const void* __restrict__ ei, int n_edges) {
    int t = blockIdx.x * blockDim.x + threadIdx.x;
    int e = t * 2;
    if (e >= n_edges) return;

    int s0, d0, s1 = -1, d1 = -1;
    bool two = (e + 1 < n_edges);
    if (d_is64) {
        const longlong2* ps = (const longlong2*)((const long long*)ei + e);
        const longlong2* pd = (const longlong2*)((const long long*)ei + n_edges + e);
        longlong2 sv = *ps;
        longlong2 dv = *pd;
        s0 = (int)sv.x; d0 = (int)dv.x;
        if (two) { s1 = (int)sv.y; d1 = (int)dv.y; }
    } else {
        const int2* ps = (const int2*)((const int*)ei + e);
        const int2* pd = (const int2*)((const int*)ei + n_edges + e);
        int2 sv = *ps;
        int2 dv = *pd;
        s0 = sv.x; d0 = dv.x;
        if (two) { s1 = sv.y; d1 = dv.y; }
    }
    histo_one(s0, d0);
    if (two) histo_one(s1, d1);
}

// ---------------------------------------------------------------------------
// Gather: warp per node, fp16 rows, packed f32x2 accumulation, unroll 8.
// ---------------------------------------------------------------------------
__device__ __forceinline__ uint2 ldcg2(const __half* p) {
    uint2 v;
    asm volatile("ld.global.cg.v2.u32 {%0,%1}, [%2];"
                 : "=r"(v.x), "=r"(v.y) : "l"(p));
    return v;
}
// acc01/acc23 are packed f32x2 (two fp32 lanes per 64-bit reg)
__device__ __forceinline__ void accp(unsigned long long& a01,
                                     unsigned long long& a23, uint2 v) {
    __half2 h01 = *(__half2*)&v.x;
    __half2 h23 = *(__half2*)&v.y;
    float2 f01 = __half22float2(h01);
    float2 f23 = __half22float2(h23);
    unsigned long long p01, p23;
    asm("mov.b64 %0, {%1, %2};" : "=l"(p01) : "f"(f01.x), "f"(f01.y));
    asm("mov.b64 %0, {%1, %2};" : "=l"(p23) : "f"(f23.x), "f"(f23.y));
    asm("add.rn.f32x2 %0, %0, %1;" : "+l"(a01) : "l"(p01));
    asm("add.rn.f32x2 %0, %0, %1;" : "+l"(a23) : "l"(p23));
}

__global__ __launch_bounds__(128)
void gather_kernel(int n_nodes) {
    int node = (blockIdx.x * blockDim.x + threadIdx.x) >> 5;
    int lane = threadIdx.x & 31;
    if (node >= n_nodes) return;

    int deg = d_deg[node];
    int nb  = min(deg, CAP);
    const size_t rb = (size_t)node * CH + lane * 4;

    unsigned long long a01 = 0, a23 = 0;
    {   // zero-init packed accumulators, then add self row
        float z = 0.0f;
        asm("mov.b64 %0, {%1, %1};" : "=l"(a01) : "f"(z));
        a23 = a01;
    }
    accp(a01, a23, ldcg2(d_xh + rb));              // self loop

    int base = node * CAP;
    for (int e0 = 0; e0 < nb; e0 += 32) {
        int idx = 0;
        if (e0 + lane < nb) idx = d_bucket[base + e0 + lane];
        int m = min(32, nb - e0);
        int t = 0;
        for (; t + 8 <= m; t += 8) {
            int s[8];
            #pragma unroll
            for (int u = 0; u < 8; u++)
                s[u] = __shfl_sync(0xFFFFFFFFu, idx, t + u);
            uint2 v[8];
            #pragma unroll
            for (int u = 0; u < 8; u++)
                v[u] = ldcg2(d_xh + (size_t)s[u] * CH + lane * 4);
            #pragma unroll
            for (int u = 0; u < 8; u++)
                accp(a01, a23, v[u]);
        }
        for (; t < m; t++) {
            int s = __shfl_sync(0xFFFFFFFFu, idx, t);
            accp(a01, a23, ldcg2(d_xh + (size_t)s * CH + lane * 4));
        }
    }
    if (deg > CAP) {   // never taken on this input
        int oc = min(d_ovf_cnt, OVF_MAX);
        for (int o = 0; o < oc; o++) {
            if (d_ovf[2 * o + 1] == node) {
                int s = d_ovf[2 * o];
                accp(a01, a23, ldcg2(d_xh + (size_t)s * CH + lane * 4));
            }
        }
    }

    float f0, f1, f2, f3;
    asm("mov.b64 {%0, %1}, %2;" : "=f"(f0), "=f"(f1) : "l"(a01));
    asm("mov.b64 {%0, %1}, %2;" : "=f"(f2), "=f"(f3) : "l"(a23));
    __half2 h01 = __floats2half2_rn(f0, f1);
    __half2 h23 = __floats2half2_rn(f2, f3);
    uint2 pack;
    pack.x = *(uint32_t*)&h01;
    pack.y = *(uint32_t*)&h23;
    *(uint2*)(d_sh + rb) = pack;
}

// ---------------------------------------------------------------------------
// Warp-MMA GEMM (plain fp16 HMMA): out = relu((s@W)/(deg+1) + bias)
// R9 config: CTA M=64 x N=128 x K=128; 8 warps, warp tile 16x64; 4 CTAs/SM.
// ---------------------------------------------------------------------------
#define SA 0
#define SB (64 * LDA * 2)                 // 17408
#define SM_TOTAL (SB + 128 * LDA * 2)     // 52224

__global__ __launch_bounds__(256, 4)
void gemm_mma_kernel(const float* __restrict__ bias,
                     float* __restrict__ out,
                     int n_nodes) {
    extern __shared__ char smem[];
    uint32_t sb = smem_to_u32(smem);
    int tid  = threadIdx.x;
    int wid  = tid >> 5;
    int lane = tid & 31;
    int row0 = blockIdx.x * 64;

    // ---- Copy A tile rows (fp16): 4 threads per row, 64 B each ----
    {
        int row = tid >> 2;              // 0..63
        int q   = tid & 3;               // quarter: 32 halfs = 64 B
        int rg  = row0 + row;
        size_t goff = (size_t)rg * CH + q * 32;
        size_t soff = ((size_t)row * LDA + q * 32) * 2;
        if (rg < n_nodes) {
            const uint4* ph = (const uint4*)(d_sh + goff);
            #pragma unroll
            for (int j = 0; j < 4; j++)
                *(uint4*)(smem + SA + soff + j * 16) = ph[j];
        } else {
            uint4 z = make_uint4(0, 0, 0, 0);
            #pragma unroll
            for (int j = 0; j < 4; j++)
                *(uint4*)(smem + SA + soff + j * 16) = z;
        }
    }
    // ---- Copy B tile (linear, 2176 uint4) ----
    {
        const uint4* sw = (const uint4*)d_Wh;
        uint4* dw = (uint4*)(smem + SB);
        #pragma unroll
        for (int i = 0; i < 9; i++) {
            int idx = tid + i * 256;
            if (idx < (128 * LDA * 2) / 16) dw[idx] = sw[idx];
        }
    }
    __syncthreads();

    // ---- Warp MMA mainloop: warp tile 16 rows x 64 cols ----
    int mw = (wid & 3) * 16;       // warp M offset (0..48)
    int nw = (wid >> 2) * 64;      // warp N offset (0 or 64)
    int lr = lane & 15;
    int lh = lane >> 4;

    float acc[8][4];
    #pragma unroll
    for (int t = 0; t < 8; t++)
        #pragma unroll
        for (int j = 0; j < 4; j++) acc[t][j] = 0.0f;

    #pragma unroll
    for (int kk = 0; kk < 8; kk++) {
        int k0 = kk * 16;
        uint32_t a[4], b[4][4];
        ldsm_x4(a, sb + SA + ((mw + lr) * LDA + k0 + lh * 8) * 2);
        #pragma unroll
        for (int nj = 0; nj < 4; nj++)
            ldsm_x4(b[nj], sb + SB + ((nw + nj * 16 + lr) * LDA + k0 + lh * 8) * 2);
        #pragma unroll
        for (int t = 0; t < 8; t++)
            mma_fp16(acc[t], a, b[t >> 1][t & 1], b[t >> 1][(t & 1) + 2]);
    }

    // ---- Epilogue: /(deg+1), +bias, relu ----
    int qr = lane >> 2;
    int qc = lane & 3;
    int ra  = row0 + mw + qr;
    int rb2 = ra + 8;
    bool va = ra < n_nodes, vb = rb2 < n_nodes;
    float inva = va ? 1.0f / (float)(d_deg[ra] + 1) : 0.0f;
    float invb = vb ? 1.0f / (float)(d_deg[rb2] + 1) : 0.0f;
    #pragma unroll
    for (int t = 0; t < 8; t++) {
        int col = nw + t * 8 + qc * 2;
        float2 bb = *(const float2*)(bias + col);
        if (va) {
            float2 o;
            o.x = fmaxf(fmaf(acc[t][0], inva, bb.x), 0.0f);
            o.y = fmaxf(fmaf(acc[t][1], inva, bb.y), 0.0f);
            *(float2*)(out + (size_t)ra * CH + col) = o;
        }
        if (vb) {
            float2 o;
            o.x = fmaxf(fmaf(acc[t][2], invb, bb.x), 0.0f);
            o.y = fmaxf(fmaf(acc[t][3], invb, bb.y), 0.0f);
            *(float2*)(out + (size_t)rb2 * CH + col) = o;
        }
    }
}

// ---------------------------------------------------------------------------
// kernel_launch — fork/join: zero+histo (main) || prep (side stream).
// Inputs: x[f32 N*128], edge_index[2*E], weight[f32 128*128],
//         u[f32 128], c[f32 1], bias[f32 128]
// u, c are dead: HEADS==1 => softmax over one element == 1.
// ---------------------------------------------------------------------------
extern "C" void kernel_launch(void* const* d_in, const int* in_sizes, int n_in,
                              void* d_out, int out_size) {
    const float* x    = (const float*)d_in[0];
    const void*  ei   = d_in[1];
    const float* W    = (const float*)d_in[2];
    const float* bias = (const float*)d_in[5];
    float* out = (float*)d_out;

    int n_nodes = in_sizes[0] / CH;
    int n_edges = in_sizes[1] / 2;

    static cudaStream_t s1 = nullptr;
    static cudaEvent_t ev0 = nullptr, ev1 = nullptr;
    if (!s1) {
        cudaFuncSetAttribute(gemm_mma_kernel,
                             cudaFuncAttributeMaxDynamicSharedMemorySize,
                             SM_TOTAL);
        cudaStreamCreateWithFlags(&s1, cudaStreamNonBlocking);
        cudaEventCreateWithFlags(&ev0, cudaEventDisableTiming);
        cudaEventCreateWithFlags(&ev1, cudaEventDisableTiming);
    }

    // Fork: prep runs on s1 in parallel with zero+histo on the main stream.
    cudaEventRecord(ev0, 0);
    cudaStreamWaitEvent(s1, ev0, 0);

    zero_kernel<<<(n_nodes + 255) / 256, 256>>>(ei, n_nodes);
    int histo_threads = (n_edges + 1) / 2;
    histo_fill_kernel<<<(histo_threads + 255) / 256, 256>>>(ei, n_edges);

    int prep_threads = n_nodes * (CH / 4);
    prep_kernel<<<(prep_threads + 255) / 256, 256, 0, s1>>>(x, W, n_nodes);
    cudaEventRecord(ev1, s1);

    // Join: gather needs both histo (main) and prep (side).
    cudaStreamWaitEvent(0, ev1, 0);
    gather_kernel<<<(n_nodes * 32 + 127) / 128, 128>>>(n_nodes);
    gemm_mma_kernel<<<(n_nodes + 63) / 64, 256, SM_TOTAL>>>(bias, out, n_nodes);
}

// round 13
// speedup vs baseline: 1.1321x; 1.1321x over previous
#include <cuda_runtime.h>
#include <cuda_fp16.h>
#include <cstdint>

// Problem constants (fixed shapes for this instance)
#define N_NODES 50000
#define N_EDGES 600000
#define CH      128          // IN_CH == OUT_CH == 128, HEADS == 1
#define CAP     96           // per-node bucket capacity
#define OVF_MAX 16384        // overflow edge list capacity (correctness fallback)

#define LDA 136              // padded fp16 row stride (272 B) for ldmatrix tiles

// ---------------------------------------------------------------------------
// Scratch (no cudaMalloc allowed)
// ---------------------------------------------------------------------------
__device__ __half d_xh[(size_t)N_NODES * CH];      // x in fp16
__device__ __half d_sh[(size_t)N_NODES * CH];      // aggregated features, fp16
__device__ int    d_deg[N_NODES];                  // in-degree (excl. self loop)
__device__ int    d_bucket[(size_t)N_NODES * CAP]; // per-dst source lists
__device__ int    d_is64;                          // edge_index dtype flag
__device__ int    d_ovf_cnt;
__device__ int    d_ovf[OVF_MAX * 2];
__device__ __half d_Wh[CH * LDA];                  // W^T [n][k], fp16, padded

// ---------------------------------------------------------------------------
// MMA helpers (baseline PTX, legal on plain sm_103)
// ---------------------------------------------------------------------------
__device__ __forceinline__ uint32_t smem_to_u32(const void* p) {
    uint32_t a;
    asm("{ .reg .u64 t; cvta.to.shared.u64 t, %1; cvt.u32.u64 %0, t; }"
        : "=r"(a) : "l"(p));
    return a;
}
__device__ __forceinline__ void ldsm_x4(uint32_t* r, uint32_t addr) {
    asm volatile("ldmatrix.sync.aligned.m8n8.x4.shared.b16 {%0,%1,%2,%3}, [%4];"
                 : "=r"(r[0]), "=r"(r[1]), "=r"(r[2]), "=r"(r[3]) : "r"(addr));
}
__device__ __forceinline__ void mma_fp16(float* c, const uint32_t* a,
                                         uint32_t b0, uint32_t b1) {
    asm volatile("mma.sync.aligned.m16n8k16.row.col.f32.f16.f16.f32 "
                 "{%0,%1,%2,%3}, {%4,%5,%6,%7}, {%8,%9}, {%0,%1,%2,%3};"
                 : "+f"(c[0]), "+f"(c[1]), "+f"(c[2]), "+f"(c[3])
                 : "r"(a[0]), "r"(a[1]), "r"(a[2]), "r"(a[3]), "r"(b0), "r"(b1));
}

// ---------------------------------------------------------------------------
// Prep: x -> fp16, W -> fp16 [n][k] padded, zero deg, sniff dtype. One launch.
// (R9 configuration: serial pipeline, no stream fork.)
// ---------------------------------------------------------------------------
__global__ void prep_kernel(const float* __restrict__ x,
                            const float* __restrict__ W,
                            const void* __restrict__ ei, int n_nodes) {
    int i = blockIdx.x * blockDim.x + threadIdx.x;
    int n4 = n_nodes * (CH / 4);
    if (i < n4) {
        float4 v = *(const float4*)(x + (size_t)i * 4);
        __half2 h01 = __floats2half2_rn(v.x, v.y);
        __half2 h23 = __floats2half2_rn(v.z, v.w);
        uint2 pack;
        pack.x = *(uint32_t*)&h01;
        pack.y = *(uint32_t*)&h23;
        *(uint2*)(d_xh + (size_t)i * 4) = pack;
    }
    if (i < n_nodes) d_deg[i] = 0;
    if (i < CH * LDA) {
        int n = i / LDA;
        int k = i % LDA;
        float w = (k < CH) ? W[(size_t)k * CH + n] : 0.0f;
        d_Wh[i] = __float2half_rn(w);
    }
    if (i == 0) {
        d_ovf_cnt = 0;
        const unsigned long long* p = (const unsigned long long*)ei;
        int is64 = 1;
        #pragma unroll
        for (int j = 0; j < 16; j++)
            if (p[j] >> 32) is64 = 0;
        d_is64 = is64;
    }
}

// ---------------------------------------------------------------------------
// Histogram + bucket fill (R9: one edge per thread)
// ---------------------------------------------------------------------------
__global__ void histo_fill_kernel(const void* __restrict__ ei, int n_edges) {
    int e = blockIdx.x * blockDim.x + threadIdx.x;
    if (e >= n_edges) return;
    int src, dst;
    if (d_is64) {
        const long long* p = (const long long*)ei;
        src = (int)p[e];
        dst = (int)p[n_edges + e];
    } else {
        const int* p = (const int*)ei;
        src = p[e];
        dst = p[n_edges + e];
    }
    int pos = atomicAdd(&d_deg[dst], 1);
    if (pos < CAP) {
        d_bucket[dst * CAP + pos] = src;
    } else {
        int j = atomicAdd(&d_ovf_cnt, 1);
        if (j < OVF_MAX) { d_ovf[2 * j] = src; d_ovf[2 * j + 1] = dst; }
    }
}

// ---------------------------------------------------------------------------
// Gather: warp per node, fp16 rows, PAIRWISE fp16 pre-add (__hadd2) then
// fp32 accumulate — 7 issues/row vs 10.
// ---------------------------------------------------------------------------
__device__ __forceinline__ uint2 ldcg2(const __half* p) {
    uint2 v;
    asm volatile("ld.global.cg.v2.u32 {%0,%1}, [%2];"
                 : "=r"(v.x), "=r"(v.y) : "l"(p));
    return v;
}
__device__ __forceinline__ void acc_h4(float* f, uint2 v) {
    __half2 h01 = *(__half2*)&v.x;
    __half2 h23 = *(__half2*)&v.y;
    float2 f01 = __half22float2(h01);
    float2 f23 = __half22float2(h23);
    f[0] += f01.x; f[1] += f01.y; f[2] += f23.x; f[3] += f23.y;
}
// accumulate a pre-added fp16 pair (half2 lanes) into fp32 acc
__device__ __forceinline__ void acc_pair(float* f, uint2 va, uint2 vb) {
    __half2 p01 = __hadd2(*(__half2*)&va.x, *(__half2*)&vb.x);
    __half2 p23 = __hadd2(*(__half2*)&va.y, *(__half2*)&vb.y);
    float2 f01 = __half22float2(p01);
    float2 f23 = __half22float2(p23);
    f[0] += f01.x; f[1] += f01.y; f[2] += f23.x; f[3] += f23.y;
}

__global__ __launch_bounds__(128)
void gather_kernel(int n_nodes) {
    int node = (blockIdx.x * blockDim.x + threadIdx.x) >> 5;
    int lane = threadIdx.x & 31;
    if (node >= n_nodes) return;

    int deg = d_deg[node];
    int nb  = min(deg, CAP);
    const size_t rb = (size_t)node * CH + lane * 4;

    float acc[4] = {0.f, 0.f, 0.f, 0.f};
    acc_h4(acc, ldcg2(d_xh + rb));                 // self loop

    int base = node * CAP;
    for (int e0 = 0; e0 < nb; e0 += 32) {
        int idx = 0;
        if (e0 + lane < nb) idx = d_bucket[base + e0 + lane];
        int m = min(32, nb - e0);
        int t = 0;
        // 4 rows per iteration: 2 independent fp16 pair-adds
        for (; t + 4 <= m; t += 4) {
            int s0 = __shfl_sync(0xFFFFFFFFu, idx, t);
            int s1 = __shfl_sync(0xFFFFFFFFu, idx, t + 1);
            int s2 = __shfl_sync(0xFFFFFFFFu, idx, t + 2);
            int s3 = __shfl_sync(0xFFFFFFFFu, idx, t + 3);
            uint2 v0 = ldcg2(d_xh + (size_t)s0 * CH + lane * 4);
            uint2 v1 = ldcg2(d_xh + (size_t)s1 * CH + lane * 4);
            uint2 v2 = ldcg2(d_xh + (size_t)s2 * CH + lane * 4);
            uint2 v3 = ldcg2(d_xh + (size_t)s3 * CH + lane * 4);
            acc_pair(acc, v0, v1);
            acc_pair(acc, v2, v3);
        }
        for (; t + 2 <= m; t += 2) {
            int s0 = __shfl_sync(0xFFFFFFFFu, idx, t);
            int s1 = __shfl_sync(0xFFFFFFFFu, idx, t + 1);
            uint2 v0 = ldcg2(d_xh + (size_t)s0 * CH + lane * 4);
            uint2 v1 = ldcg2(d_xh + (size_t)s1 * CH + lane * 4);
            acc_pair(acc, v0, v1);
        }
        for (; t < m; t++) {
            int s = __shfl_sync(0xFFFFFFFFu, idx, t);
            acc_h4(acc, ldcg2(d_xh + (size_t)s * CH + lane * 4));
        }
    }
    if (deg > CAP) {   // never taken on this input
        int oc = min(d_ovf_cnt, OVF_MAX);
        for (int o = 0; o < oc; o++) {
            if (d_ovf[2 * o + 1] == node) {
                int s = d_ovf[2 * o];
                acc_h4(acc, ldcg2(d_xh + (size_t)s * CH + lane * 4));
            }
        }
    }

    __half2 h01 = __floats2half2_rn(acc[0], acc[1]);
    __half2 h23 = __floats2half2_rn(acc[2], acc[3]);
    uint2 pack;
    pack.x = *(uint32_t*)&h01;
    pack.y = *(uint32_t*)&h23;
    *(uint2*)(d_sh + rb) = pack;
}

// ---------------------------------------------------------------------------
// Warp-MMA GEMM (plain fp16 HMMA): out = relu((s@W)/(deg+1) + bias)
// R9 config: CTA M=64 x N=128 x K=128; 8 warps, warp tile 16x64; 4 CTAs/SM.
// ---------------------------------------------------------------------------
#define SA 0
#define SB (64 * LDA * 2)                 // 17408
#define SM_TOTAL (SB + 128 * LDA * 2)     // 52224

__global__ __launch_bounds__(256, 4)
void gemm_mma_kernel(const float* __restrict__ bias,
                     float* __restrict__ out,
                     int n_nodes) {
    extern __shared__ char smem[];
    uint32_t sb = smem_to_u32(smem);
    int tid  = threadIdx.x;
    int wid  = tid >> 5;
    int lane = tid & 31;
    int row0 = blockIdx.x * 64;

    // ---- Copy A tile rows (fp16): 4 threads per row, 64 B each ----
    {
        int row = tid >> 2;              // 0..63
        int q   = tid & 3;               // quarter: 32 halfs = 64 B
        int rg  = row0 + row;
        size_t goff = (size_t)rg * CH + q * 32;
        size_t soff = ((size_t)row * LDA + q * 32) * 2;
        if (rg < n_nodes) {
            const uint4* ph = (const uint4*)(d_sh + goff);
            #pragma unroll
            for (int j = 0; j < 4; j++)
                *(uint4*)(smem + SA + soff + j * 16) = ph[j];
        } else {
            uint4 z = make_uint4(0, 0, 0, 0);
            #pragma unroll
            for (int j = 0; j < 4; j++)
                *(uint4*)(smem + SA + soff + j * 16) = z;
        }
    }
    // ---- Copy B tile (linear, 2176 uint4) ----
    {
        const uint4* sw = (const uint4*)d_Wh;
        uint4* dw = (uint4*)(smem + SB);
        #pragma unroll
        for (int i = 0; i < 9; i++) {
            int idx = tid + i * 256;
            if (idx < (128 * LDA * 2) / 16) dw[idx] = sw[idx];
        }
    }
    __syncthreads();

    // ---- Warp MMA mainloop: warp tile 16 rows x 64 cols ----
    int mw = (wid & 3) * 16;       // warp M offset (0..48)
    int nw = (wid >> 2) * 64;      // warp N offset (0 or 64)
    int lr = lane & 15;
    int lh = lane >> 4;

    float acc[8][4];
    #pragma unroll
    for (int t = 0; t < 8; t++)
        #pragma unroll
        for (int j = 0; j < 4; j++) acc[t][j] = 0.0f;

    #pragma unroll
    for (int kk = 0; kk < 8; kk++) {
        int k0 = kk * 16;
        uint32_t a[4], b[4][4];
        ldsm_x4(a, sb + SA + ((mw + lr) * LDA + k0 + lh * 8) * 2);
        #pragma unroll
        for (int nj = 0; nj < 4; nj++)
            ldsm_x4(b[nj], sb + SB + ((nw + nj * 16 + lr) * LDA + k0 + lh * 8) * 2);
        #pragma unroll
        for (int t = 0; t < 8; t++)
            mma_fp16(acc[t], a, b[t >> 1][t & 1], b[t >> 1][(t & 1) + 2]);
    }

    // ---- Epilogue: /(deg+1), +bias, relu ----
    int qr = lane >> 2;
    int qc = lane & 3;
    int ra  = row0 + mw + qr;
    int rb2 = ra + 8;
    bool va = ra < n_nodes, vb = rb2 < n_nodes;
    float inva = va ? 1.0f / (float)(d_deg[ra] + 1) : 0.0f;
    float invb = vb ? 1.0f / (float)(d_deg[rb2] + 1) : 0.0f;
    #pragma unroll
    for (int t = 0; t < 8; t++) {
        int col = nw + t * 8 + qc * 2;
        float2 bb = *(const float2*)(bias + col);
        if (va) {
            float2 o;
            o.x = fmaxf(fmaf(acc[t][0], inva, bb.x), 0.0f);
            o.y = fmaxf(fmaf(acc[t][1], inva, bb.y), 0.0f);
            *(float2*)(out + (size_t)ra * CH + col) = o;
        }
        if (vb) {
            float2 o;
            o.x = fmaxf(fmaf(acc[t][2], invb, bb.x), 0.0f);
            o.y = fmaxf(fmaf(acc[t][3], invb, bb.y), 0.0f);
            *(float2*)(out + (size_t)rb2 * CH + col) = o;
        }
    }
}

// ---------------------------------------------------------------------------
// kernel_launch (R9 serial structure)
// Inputs: x[f32 N*128], edge_index[2*E], weight[f32 128*128],
//         u[f32 128], c[f32 1], bias[f32 128]
// u, c are dead: HEADS==1 => softmax over one element == 1.
// ---------------------------------------------------------------------------
extern "C" void kernel_launch(void* const* d_in, const int* in_sizes, int n_in,
                              void* d_out, int out_size) {
    const float* x    = (const float*)d_in[0];
    const void*  ei   = d_in[1];
    const float* W    = (const float*)d_in[2];
    const float* bias = (const float*)d_in[5];
    float* out = (float*)d_out;

    int n_nodes = in_sizes[0] / CH;
    int n_edges = in_sizes[1] / 2;

    static bool attr_set = false;
    if (!attr_set) {
        cudaFuncSetAttribute(gemm_mma_kernel,
                             cudaFuncAttributeMaxDynamicSharedMemorySize,
                             SM_TOTAL);
        attr_set = true;
    }

    int prep_threads = n_nodes * (CH / 4);        // 1.6M, covers all prep work
    prep_kernel<<<(prep_threads + 255) / 256, 256>>>(x, W, ei, n_nodes);
    histo_fill_kernel<<<(n_edges + 255) / 256, 256>>>(ei, n_edges);
    gather_kernel<<<(n_nodes * 32 + 127) / 128, 128>>>(n_nodes);
    gemm_mma_kernel<<<(n_nodes + 63) / 64, 256, SM_TOTAL>>>(bias, out, n_nodes);
}